// round 9
// baseline (speedup 1.0000x reference)
#include <cuda_runtime.h>
#include <cstdint>

// Problem constants
#define BB     64
#define SS     2048
#define INDIM  512
#define HH     512
#define CL     8            // cluster size (j-split of W_hh)
#define NCTA   128          // 16 clusters x 8 CTAs

typedef unsigned long long ull;

// ---------------- packed f32x2 helpers (FFMA2 path, sm_103a) ----------------
__device__ __forceinline__ void ffma2(ull& acc, ull a, ull b) {
    asm volatile("fma.rn.f32x2 %0, %1, %2, %0;" : "+l"(acc) : "l"(a), "l"(b));
}
__device__ __forceinline__ ull pack2(float x) {
    ull r; asm("mov.b64 %0, {%1, %1};" : "=l"(r) : "f"(x)); return r;
}
__device__ __forceinline__ ull packf2(float x, float y) {
    ull r; asm("mov.b64 %0, {%1, %2};" : "=l"(r) : "f"(x), "f"(y)); return r;
}
__device__ __forceinline__ float2 unpack2(ull v) {
    float2 r; asm("mov.b64 {%0, %1}, %2;" : "=f"(r.x), "=f"(r.y) : "l"(v)); return r;
}
__device__ __forceinline__ uint32_t smem_u32(const void* p) {
    uint32_t a;
    asm("{ .reg .u64 t; cvta.to.shared.u64 t, %1; cvt.u32.u64 %0, t; }" : "=r"(a) : "l"(p));
    return a;
}
__device__ __forceinline__ uint32_t mapa_rank(uint32_t laddr, uint32_t rank) {
    uint32_t r;
    asm("mapa.shared::cluster.u32 %0, %1, %2;" : "=r"(r) : "r"(laddr), "r"(rank));
    return r;
}
// plain (weak) remote DSMEM store — direct crossbar, no async-proxy engine
__device__ __forceinline__ void st_cluster_b64(uint32_t raddr, ull v) {
    asm volatile("st.shared::cluster.b64 [%0], %1;" :: "r"(raddr), "l"(v) : "memory");
}
// relaxed cluster-scope flag store (paired with a preceding cumulative fence)
__device__ __forceinline__ void st_flag_cluster(uint32_t raddr, unsigned v) {
    asm volatile("st.relaxed.cluster.shared::cluster.u32 [%0], %1;"
                 :: "r"(raddr), "r"(v) : "memory");
}
__device__ __forceinline__ unsigned ld_acq_sh(uint32_t addr) {
    unsigned v;
    asm volatile("ld.acquire.cluster.shared::cta.u32 %0, [%1];"
                 : "=r"(v) : "r"(addr) : "memory");
    return v;
}
__device__ __forceinline__ void fence_cluster() {
    asm volatile("fence.acq_rel.cluster;" ::: "memory");
}

// ---------------- Phase 1: x_proj = inputs @ W_ih^T + b_ih ----------------
__global__ __launch_bounds__(256) void xproj_kernel(
    const float* __restrict__ A, const float* __restrict__ W,
    const float* __restrict__ bias, float* __restrict__ C) {
    __shared__ float As[16][132];
    __shared__ float Bs[16][132];

    const int tid = threadIdx.x;
    const int m0 = blockIdx.x * 128;
    const int n0 = blockIdx.y * 128;
    const int lr = tid >> 2;
    const int lk = (tid & 3) << 2;
    const int tx = tid & 15;
    const int ty = tid >> 4;

    ull acc[8][4];
#pragma unroll
    for (int i = 0; i < 8; i++)
#pragma unroll
        for (int j = 0; j < 4; j++) acc[i][j] = 0ull;

    for (int k0 = 0; k0 < INDIM; k0 += 16) {
        float4 a0 = *(const float4*)(A + (size_t)(m0 + lr) * INDIM + k0 + lk);
        float4 a1 = *(const float4*)(A + (size_t)(m0 + lr + 64) * INDIM + k0 + lk);
        float4 w0 = *(const float4*)(W + (size_t)(n0 + lr) * INDIM + k0 + lk);
        float4 w1 = *(const float4*)(W + (size_t)(n0 + lr + 64) * INDIM + k0 + lk);
        __syncthreads();
        As[lk + 0][lr] = a0.x; As[lk + 1][lr] = a0.y; As[lk + 2][lr] = a0.z; As[lk + 3][lr] = a0.w;
        As[lk + 0][lr + 64] = a1.x; As[lk + 1][lr + 64] = a1.y; As[lk + 2][lr + 64] = a1.z; As[lk + 3][lr + 64] = a1.w;
        Bs[lk + 0][lr] = w0.x; Bs[lk + 1][lr] = w0.y; Bs[lk + 2][lr] = w0.z; Bs[lk + 3][lr] = w0.w;
        Bs[lk + 0][lr + 64] = w1.x; Bs[lk + 1][lr + 64] = w1.y; Bs[lk + 2][lr + 64] = w1.z; Bs[lk + 3][lr + 64] = w1.w;
        __syncthreads();
#pragma unroll
        for (int k = 0; k < 16; k++) {
            float4 am0 = *(const float4*)&As[k][ty * 4];
            float4 am1 = *(const float4*)&As[k][64 + ty * 4];
            ulonglong2 bn0 = *(const ulonglong2*)&Bs[k][tx * 4];
            ulonglong2 bn1 = *(const ulonglong2*)&Bs[k][64 + tx * 4];
            float am[8] = {am0.x, am0.y, am0.z, am0.w, am1.x, am1.y, am1.z, am1.w};
#pragma unroll
            for (int i = 0; i < 8; i++) {
                ull ap = pack2(am[i]);
                ffma2(acc[i][0], ap, bn0.x);
                ffma2(acc[i][1], ap, bn0.y);
                ffma2(acc[i][2], ap, bn1.x);
                ffma2(acc[i][3], ap, bn1.y);
            }
        }
    }

    float4 bA = *(const float4*)(bias + n0 + tx * 4);
    float4 bBv = *(const float4*)(bias + n0 + 64 + tx * 4);
#pragma unroll
    for (int i = 0; i < 8; i++) {
        int m = m0 + ((i < 4) ? (ty * 4 + i) : (64 + ty * 4 + (i - 4)));
        float2 c0 = unpack2(acc[i][0]);
        float2 c1 = unpack2(acc[i][1]);
        float2 c2 = unpack2(acc[i][2]);
        float2 c3 = unpack2(acc[i][3]);
        float4 o0 = make_float4(c0.x + bA.x, c0.y + bA.y, c1.x + bA.z, c1.y + bA.w);
        float4 o1 = make_float4(c2.x + bBv.x, c2.y + bBv.y, c3.x + bBv.z, c3.y + bBv.w);
        *(float4*)(C + (size_t)m * HH + n0 + tx * 4) = o0;
        *(float4*)(C + (size_t)m * HH + n0 + 64 + tx * 4) = o1;
    }
}

// ---------------- Phase 2: scan with direct-DSMEM push + local flag poll ---
// Cluster of 8 CTAs = 4 batches in 2 groups of 2. Rank r owns j in
// [64r,64r+64); W slice in registers. Producers push packed h values straight
// into every rank's hsp slot with plain st.shared::cluster.b64 (no engine),
// then publish a monotonic step tag into each rank's LOCAL flag array.
// Consumers spin on their own smem flags (cheap LDS poll, no fabric traffic).
__global__ __launch_bounds__(256, 1) __cluster_dims__(CL, 1, 1)
void rnn_scan_kernel(
    const float* __restrict__ h0, const float* __restrict__ W_hh,
    const float* __restrict__ b_hh, float* __restrict__ out, int write_hfinal) {
    __shared__ __align__(16) ull hsp[2][2][256][2];   // [grp][slot][kp][b] 16KB
    __shared__ float red[2][2][8][32][2];             // [grp][jpar][w][jp][b] 8KB
    __shared__ unsigned flg[2][2][8];                 // [grp][slot][src rank]

    const int tid = threadIdx.x;
    const int w = tid >> 5;           // warp -> k-chunk [64w, 64w+64)
    const int l = tid & 31;           // lane -> j-pair {2l, 2l+1}
    uint32_t rank;
    asm("mov.u32 %0, %%cluster_ctarank;" : "=r"(rank));
    const int j0 = (int)rank * 64;
    const int b0 = (blockIdx.x >> 3) * 4;
    const int obl = (tid >> 6) & 1;   // batch within group (tid<128 active)
    const int oj = tid & 63;          // j within slice
    const int gj = j0 + oj;

    // ---- W slice into registers, k-paired ----
    ull Wp0[32], Wp1[32];
    {
        const ull* w0p = (const ull*)(W_hh + (size_t)(j0 + 2 * l) * HH + w * 64);
        const ull* w1p = (const ull*)(W_hh + (size_t)(j0 + 2 * l + 1) * HH + w * 64);
#pragma unroll
        for (int p = 0; p < 32; p++) { Wp0[p] = w0p[p]; Wp1[p] = w1p[p]; }
    }
    const float bh = b_hh[gj];

    // ---- init h slot 0 of both groups from h0; init flags ----
#pragma unroll
    for (int g = 0; g < 2; g++) {
        float* hf = (float*)&hsp[g][0][0][0];
        for (int i = tid; i < 2 * HH; i += 256) {
            int b = i >> 9, k = i & 511;
            hf[(k >> 1) * 4 + b * 2 + (k & 1)] = h0[(size_t)(b0 + 2 * g + b) * HH + k];
        }
    }
    if (tid < 32) {                    // flg[g][s][r]: slot0 pre-tagged with 1
        int g = tid >> 4, s = (tid >> 3) & 1, r = tid & 7;
        flg[g][s][r] = (s == 0) ? 1u : 0u;
    }
    __syncthreads();
    asm volatile("barrier.cluster.arrive.aligned;" ::: "memory");
    asm volatile("barrier.cluster.wait.aligned;" ::: "memory");

    // remote addresses
    const uint32_t hbase = smem_u32(&hsp[0][0][0][0]);
    const uint32_t fbase = smem_u32(&flg[0][0][0]);
    // producer data targets: my (b,oj-pair) lands at ull index (32*rank+m)*2+obl
    const uint32_t myoff = (uint32_t)(((32 * (int)rank + (oj >> 1)) * 2 + obl) * 8);
    uint32_t rh[CL];
#pragma unroll
    for (int r = 0; r < CL; r++) rh[r] = mapa_rank(hbase, (uint32_t)r) + myoff;
    // flag pusher (tid<8): remote flag base for rank 'tid', my source slot
    const uint32_t rfa = mapa_rank(fbase, (uint32_t)(tid & 7)) + rank * 4u;

    const size_t obA = (size_t)(b0 + obl) * SS * HH + gj;
    const size_t obB = (size_t)(b0 + 2 + obl) * SS * HH + gj;
    float xpA = 0.f, xpB = 0.f, hlA = 0.f, hlB = 0.f;
    if (tid < 128) { xpA = __ldcs(out + obA); xpB = __ldcs(out + obB); }

#define GSTEP(T, S, G, XP, HL, OB)                                             \
  {                                                                            \
    { const uint32_t fa = fbase + (uint32_t)((((G) * 2 + (S)) * 8 + (l & 7)) * 4);\
      const unsigned tg = (unsigned)(T) + 1u;                                  \
      while (__ballot_sync(0xffffffffu, (int)(ld_acq_sh(fa) - tg) >= 0)        \
             != 0xffffffffu) { } }                                             \
    const ull* hb = &hsp[G][S][w * 32][0];                                     \
    ull a00 = 0, a01 = 0, a10 = 0, a11 = 0;                                    \
    _Pragma("unroll")                                                          \
    for (int p = 0; p < 32; p++) {                                             \
      ulonglong2 hx = *(const ulonglong2*)(hb + p * 2);                        \
      ull w0 = Wp0[p], w1 = Wp1[p];                                            \
      ffma2(a00, hx.x, w0); ffma2(a01, hx.y, w0);                              \
      ffma2(a10, hx.x, w1); ffma2(a11, hx.y, w1);                              \
    }                                                                          \
    { float2 f; float2 ra, rb;                                                 \
      f = unpack2(a00); ra.x = f.x + f.y; f = unpack2(a01); ra.y = f.x + f.y;  \
      f = unpack2(a10); rb.x = f.x + f.y; f = unpack2(a11); rb.y = f.x + f.y;  \
      *(float2*)&red[G][0][w][l][0] = ra;                                      \
      *(float2*)&red[G][1][w][l][0] = rb; }                                    \
    __syncthreads();                                                           \
    float hv = 0.f;                                                            \
    if (tid < 128) {                                                           \
      const float* rf = &red[G][oj & 1][0][oj >> 1][obl];                      \
      float sum = rf[0] + rf[64] + rf[128] + rf[192]                           \
                + rf[256] + rf[320] + rf[384] + rf[448];                       \
      float pre = XP + sum + bh;                                               \
      float e = __expf(pre + pre);                                             \
      hv = 1.f - __fdividef(2.f, e + 1.f);                                     \
      float hvn = __shfl_down_sync(0xffffffffu, hv, 1);                        \
      if (((T) + 1 < SS) && !(oj & 1)) {                                       \
        ull v = packf2(hv, hvn);                                               \
        const uint32_t so = (uint32_t)((G) * 8192 + ((S) ^ 1) * 4096);         \
        _Pragma("unroll")                                                      \
        for (int r = 0; r < CL; r++) st_cluster_b64(rh[r] + so, v);            \
      }                                                                        \
    }                                                                          \
    __syncthreads();                                                           \
    if (((T) + 1 < SS) && tid < 8) {                                           \
      fence_cluster();                                                         \
      st_flag_cluster(rfa + (uint32_t)((((G) * 2 + ((S) ^ 1)) * 8) * 4),       \
                      (unsigned)(T) + 2u);                                     \
    }                                                                          \
    if (tid < 128) {                                                           \
      __stcs(out + OB + (size_t)(T) * HH, hv);                                 \
      HL = hv;                                                                 \
      if ((T) + 1 < SS) XP = __ldcs(out + OB + (size_t)((T) + 1) * HH);        \
    }                                                                          \
  }

    for (int t = 0; t < SS; t += 2) {
        GSTEP(t,     0, 0, xpA, hlA, obA);
        GSTEP(t,     0, 1, xpB, hlB, obB);
        GSTEP(t + 1, 1, 0, xpA, hlA, obA);
        GSTEP(t + 1, 1, 1, xpB, hlB, obB);
    }
#undef GSTEP

    if (write_hfinal && tid < 128) {
        out[(size_t)BB * SS * HH + (size_t)(b0 + obl) * HH + gj] = hlA;
        out[(size_t)BB * SS * HH + (size_t)(b0 + 2 + obl) * HH + gj] = hlB;
    }
}

// ---------------- launch ----------------
extern "C" void kernel_launch(void* const* d_in, const int* in_sizes, int n_in,
                              void* d_out, int out_size) {
    const float* inputs = (const float*)d_in[0];   // [64, 2048, 512]
    const float* h0     = (const float*)d_in[1];   // [64, 512]
    const float* W_ih   = (const float*)d_in[2];   // [512, 512]
    const float* W_hh   = (const float*)d_in[3];   // [512, 512]
    const float* b_ih   = (const float*)d_in[4];   // [512]
    const float* b_hh   = (const float*)d_in[5];   // [512]
    float* out = (float*)d_out;

    // Phase 1: x_proj into the outs region of d_out (scan overwrites in place)
    dim3 g1((BB * SS) / 128, HH / 128, 1);
    xproj_kernel<<<g1, 256>>>(inputs, W_ih, b_ih, out);

    // Phase 2: 16 clusters of 8 CTAs; direct DSMEM push + local-flag poll
    long long need = (long long)BB * SS * HH + (long long)BB * HH;
    int wf = ((long long)out_size >= need) ? 1 : 0;
    rnn_scan_kernel<<<NCTA, 256>>>(h0, W_hh, b_hh, out, wf);
}